// round 10
// baseline (speedup 1.0000x reference)
#include <cuda_runtime.h>
#include <math.h>
#include <stdint.h>

// R9: cp.async 4-stage pipelined tf32 GEMMs (weights pre-converted to tf32,
// A converted at fragment load), QKV batched via grid.z. Attention = R8.

#define BATCH 4
#define LSEQ  2048
#define SSEQ  2048
#define DMODEL 1024
#define NHEAD 16
#define EDIM  64
#define MTOT  (BATCH * LSEQ)

// ---------------------------------------------------------------------------
// helpers
// ---------------------------------------------------------------------------
__device__ __forceinline__ uint32_t f2tf(float f) {
    uint32_t r; asm("cvt.rna.tf32.f32 %0, %1;" : "=r"(r) : "f"(f));
    return r;
}
__device__ __forceinline__ void mma_tf32(float d[4], uint32_t a0, uint32_t a1,
                                         uint32_t a2, uint32_t a3,
                                         uint32_t b0, uint32_t b1) {
    asm volatile(
        "mma.sync.aligned.m16n8k8.row.col.f32.tf32.tf32.f32 "
        "{%0,%1,%2,%3}, {%4,%5,%6,%7}, {%8,%9}, {%0,%1,%2,%3};"
        : "+f"(d[0]), "+f"(d[1]), "+f"(d[2]), "+f"(d[3])
        : "r"(a0), "r"(a1), "r"(a2), "r"(a3), "r"(b0), "r"(b1));
}
__device__ __forceinline__ uint32_t smem_u32(const void* p) {
    uint32_t a;
    asm("{ .reg .u64 t; cvta.to.shared.u64 t, %1; cvt.u32.u64 %0, t; }" : "=r"(a) : "l"(p));
    return a;
}
__device__ __forceinline__ void cpa16(uint32_t dst, const void* src) {
    asm volatile("cp.async.cg.shared.global [%0], [%1], 16;" :: "r"(dst), "l"(src));
}
__device__ __forceinline__ void cpa_commit() {
    asm volatile("cp.async.commit_group;" ::: "memory");
}
__device__ __forceinline__ void cpa_wait2() {
    asm volatile("cp.async.wait_group 2;" ::: "memory");
}
__device__ __forceinline__ void cpa_wait0() {
    asm volatile("cp.async.wait_group 0;" ::: "memory");
}
// granule swizzle (attention): rotate each 8-granule block by 2*(block idx)
__device__ __forceinline__ int swz(int pos) {
    const int g4 = pos >> 2;
    return (((g4 & ~7) | ((g4 + 2 * (g4 >> 3)) & 7)) << 2) | (pos & 3);
}

// ---------------------------------------------------------------------------
// Scratch
// ---------------------------------------------------------------------------
__device__ float g_q[MTOT * DMODEL];
__device__ float g_k[MTOT * DMODEL];
__device__ float g_v[MTOT * DMODEL];
__device__ float g_attn[MTOT * DMODEL];
__device__ float g_wq[DMODEL * DMODEL];
__device__ float g_wk[DMODEL * DMODEL];
__device__ float g_wv[DMODEL * DMODEL];
__device__ float g_wo[DMODEL * DMODEL];

// ---------------------------------------------------------------------------
// weight pre-convert: dst = tf32_rna(src), 1M floats per z
// ---------------------------------------------------------------------------
struct WC { const float* src[4]; float* dst[4]; };
__global__ __launch_bounds__(256) void wconv_kernel(WC p) {
    const float* s = p.src[blockIdx.y];
    float* d = p.dst[blockIdx.y];
    const int i = (blockIdx.x * 256 + threadIdx.x) * 4;
    float4 v = *(const float4*)(s + i);
    v.x = __uint_as_float(f2tf(v.x));
    v.y = __uint_as_float(f2tf(v.y));
    v.z = __uint_as_float(f2tf(v.z));
    v.w = __uint_as_float(f2tf(v.w));
    *(float4*)(d + i) = v;
}

// ---------------------------------------------------------------------------
// tf32 GEMM, cp.async 4-stage: C[8192,1024] = A @ Wtf32 + bias
// A raw fp32 in smem (cvt at fragment load); W pre-converted tf32 bits.
// 128x128 tile, BK=16, 256 thr, batched over grid.z.
// ---------------------------------------------------------------------------
#define GEMM_N 1024
#define GEMM_K 1024
#define BK 16
#define ASTR 20
#define BSTR 136
#define A_STG (128 * ASTR)          // 2560 words
#define B_STG (BK * BSTR)           // 2176 words
#define GEMM_SMEM_WORDS (4 * A_STG + 4 * B_STG)
#define GEMM_SMEM_BYTES (GEMM_SMEM_WORDS * 4)

struct G3 { const float* A[3]; const float* W[3]; const float* B[3]; float* C[3]; };

__global__ __launch_bounds__(256, 2) void gemm_tf32_kernel(G3 p) {
    extern __shared__ uint32_t dsm[];
    const int z = blockIdx.z;
    const float* __restrict__ A = p.A[z];
    const float* __restrict__ W = p.W[z];
    const float* __restrict__ bias = p.B[z];
    float* __restrict__ C = p.C[z];

    const int tid = threadIdx.x;
    const int wid = tid >> 5;
    const int lane = tid & 31;
    const int gidr = lane >> 2;
    const int tig  = lane & 3;
    const int m_base = blockIdx.y * 128;
    const int n_base = blockIdx.x * 128;
    const int warp_m = (wid & 3) * 32;
    const int warp_n = (wid >> 2) * 64;

    const int ar0 = tid >> 2;
    const int aq  = tid & 3;
    const int br0 = tid >> 5;
    const int bq  = tid & 31;

    const uint32_t smem_base = smem_u32(dsm);

    // cp.async dst addresses per stage (bytes)
    const uint32_t a_dst0 = smem_base + (ar0 * ASTR + aq * 4) * 4;
    const uint32_t a_dst1 = smem_base + ((ar0 + 64) * ASTR + aq * 4) * 4;
    const uint32_t b_dst0 = smem_base + (4 * A_STG + br0 * BSTR + bq * 4) * 4;
    const uint32_t b_dst1 = smem_base + (4 * A_STG + (br0 + 8) * BSTR + bq * 4) * 4;

    const float* a_src0 = A + (size_t)(m_base + ar0) * GEMM_K + aq * 4;
    const float* a_src1 = A + (size_t)(m_base + ar0 + 64) * GEMM_K + aq * 4;
    const float* b_src0 = W + (size_t)br0 * GEMM_N + n_base + bq * 4;
    const float* b_src1 = W + (size_t)(br0 + 8) * GEMM_N + n_base + bq * 4;

    float acc[2][8][4];
    #pragma unroll
    for (int ma = 0; ma < 2; ma++)
        #pragma unroll
        for (int na = 0; na < 8; na++)
            #pragma unroll
            for (int f = 0; f < 4; f++) acc[ma][na][f] = 0.0f;

    const int NSTAGE = GEMM_K / BK;   // 64

    // prologue: stages 0,1,2
    #pragma unroll
    for (int s = 0; s < 3; s++) {
        const uint32_t ao = s * A_STG * 4;
        const uint32_t bo = s * B_STG * 4;
        cpa16(a_dst0 + ao, a_src0 + s * BK);
        cpa16(a_dst1 + ao, a_src1 + s * BK);
        cpa16(b_dst0 + bo, b_src0 + (size_t)s * BK * GEMM_N);
        cpa16(b_dst1 + bo, b_src1 + (size_t)s * BK * GEMM_N);
        cpa_commit();
    }

    for (int t = 0; t < NSTAGE; t++) {
        if (t < NSTAGE - 3) cpa_wait2(); else cpa_wait0();
        __syncthreads();

        // issue stage t+3 (buffers (t+3)&3 == (t-1)&3, free after this sync)
        if (t + 3 < NSTAGE) {
            const int s = t + 3;
            const int sb = s & 3;
            const uint32_t ao = sb * A_STG * 4;
            const uint32_t bo = sb * B_STG * 4;
            cpa16(a_dst0 + ao, a_src0 + s * BK);
            cpa16(a_dst1 + ao, a_src1 + s * BK);
            cpa16(b_dst0 + bo, b_src0 + (size_t)s * BK * GEMM_N);
            cpa16(b_dst1 + bo, b_src1 + (size_t)s * BK * GEMM_N);
        }
        cpa_commit();

        const uint32_t* a_s = dsm + (t & 3) * A_STG;
        const uint32_t* b_s = dsm + 4 * A_STG + (t & 3) * B_STG;

        #pragma unroll
        for (int kk = 0; kk < 2; kk++) {
            const int kb = kk * 8;
            uint32_t af[2][4];
            #pragma unroll
            for (int ma = 0; ma < 2; ma++) {
                const uint32_t* ap = &a_s[(warp_m + ma * 16 + gidr) * ASTR + kb + tig];
                af[ma][0] = f2tf(__uint_as_float(ap[0]));
                af[ma][1] = f2tf(__uint_as_float(ap[8 * ASTR]));
                af[ma][2] = f2tf(__uint_as_float(ap[4]));
                af[ma][3] = f2tf(__uint_as_float(ap[8 * ASTR + 4]));
            }
            #pragma unroll
            for (int na = 0; na < 8; na++) {
                const uint32_t* bp = &b_s[(kb + tig) * BSTR + warp_n + na * 8 + gidr];
                const uint32_t b0 = bp[0];
                const uint32_t b1 = bp[4 * BSTR];
                mma_tf32(acc[0][na], af[0][0], af[0][1], af[0][2], af[0][3], b0, b1);
                mma_tf32(acc[1][na], af[1][0], af[1][1], af[1][2], af[1][3], b0, b1);
            }
        }
        __syncthreads();
    }

    #pragma unroll
    for (int na = 0; na < 8; na++) {
        const int col = n_base + warp_n + na * 8 + tig * 2;
        const float bx = __ldg(bias + col);
        const float by = __ldg(bias + col + 1);
        #pragma unroll
        for (int ma = 0; ma < 2; ma++) {
            const int r0 = m_base + warp_m + ma * 16 + gidr;
            float2 lo = make_float2(acc[ma][na][0] + bx, acc[ma][na][1] + by);
            float2 hi = make_float2(acc[ma][na][2] + bx, acc[ma][na][3] + by);
            *(float2*)(C + (size_t)r0 * GEMM_N + col)       = lo;
            *(float2*)(C + (size_t)(r0 + 8) * GEMM_N + col) = hi;
        }
    }
}

// ---------------------------------------------------------------------------
// Flash attention via tf32 mma.sync, swizzled smem (unchanged from R8)
// ---------------------------------------------------------------------------
#define PSTR 132
#define KSTR 68
#define VSTR 132
#define PS_W 0
#define KS_W 16896
#define VS_W 25600
#define ATTN_SMEM_WORDS 34048
#define ATTN_SMEM_BYTES (ATTN_SMEM_WORDS * 4)

__global__ __launch_bounds__(256, 1) void attn_mma_kernel(
    const float* __restrict__ gq, const float* __restrict__ gk,
    const float* __restrict__ gv, float* __restrict__ go)
{
    extern __shared__ uint32_t sm[];
    uint32_t* p_s = sm + PS_W;
    uint32_t* k_s = sm + KS_W;
    uint32_t* v_s = sm + VS_W;

    const int bh = blockIdx.y;
    const int b = bh >> 4;
    const int h = bh & 15;
    const int q0 = blockIdx.x * 128;
    const int tid = threadIdx.x;
    const int wid = tid >> 5;
    const int lane = tid & 31;
    const int g = lane >> 2;
    const int t = lane & 3;
    const int qrow = wid * 16;

    const float* qbase = gq + (size_t)b * LSEQ * DMODEL + h * EDIM;
    const float* kbase = gk + (size_t)b * SSEQ * DMODEL + h * EDIM;
    const float* vbase = gv + (size_t)b * SSEQ * DMODEL + h * EDIM;

    int fo16[4], fo32[8];
    #pragma unroll
    for (int u = 0; u < 4; u++) fo16[u] = swz(t * 16 + u * 4);
    #pragma unroll
    for (int u = 0; u < 8; u++) fo32[u] = swz(t * 32 + u * 4);

    const int eqc = tid & 15;
    int stg16[4];
    #pragma unroll
    for (int c = 0; c < 4; c++) stg16[c] = swz(c * 16 + eqc);

    #pragma unroll
    for (int it = 0; it < 8; it++) {
        const int r = (tid >> 4) + 16 * it;
        float4 qv = *(const float4*)(qbase + (size_t)(q0 + r) * DMODEL + eqc * 4);
        uint32_t* dst = p_s + r * PSTR;
        dst[stg16[0]] = f2tf(qv.x * 0.125f);
        dst[stg16[1]] = f2tf(qv.y * 0.125f);
        dst[stg16[2]] = f2tf(qv.z * 0.125f);
        dst[stg16[3]] = f2tf(qv.w * 0.125f);
    }
    __syncthreads();

    uint32_t qa[16], qb[16];
    {
        const uint32_t* r0 = p_s + (qrow + g) * PSTR;
        const uint32_t* r1 = p_s + (qrow + g + 8) * PSTR;
        #pragma unroll
        for (int u = 0; u < 4; u++) {
            *(uint4*)&qa[u * 4] = *(const uint4*)&r0[fo16[u]];
            *(uint4*)&qb[u * 4] = *(const uint4*)&r1[fo16[u]];
        }
    }

    float m0 = -1e30f, m1 = -1e30f, l0 = 0.0f, l1 = 0.0f;
    float av[8][4];
    #pragma unroll
    for (int nt = 0; nt < 8; nt++)
        #pragma unroll
        for (int f = 0; f < 4; f++) av[nt][f] = 0.0f;

    const int pj0 = ((2 * t) & 3) * 32 + ((2 * t) >> 2);
    const int pj1 = ((2 * t + 1) & 3) * 32 + ((2 * t + 1) >> 2);

    for (int s0 = 0; s0 < SSEQ; s0 += 128) {
        __syncthreads();

        #pragma unroll
        for (int it = 0; it < 8; it++) {
            const int r = (tid >> 4) + 16 * it;
            float4 kv = *(const float4*)(kbase + (size_t)(s0 + r) * DMODEL + eqc * 4);
            uint32_t* dst = k_s + r * KSTR;
            dst[stg16[0]] = f2tf(kv.x);
            dst[stg16[1]] = f2tf(kv.y);
            dst[stg16[2]] = f2tf(kv.z);
            dst[stg16[3]] = f2tf(kv.w);
        }
        #pragma unroll
        for (int it = 0; it < 8; it++) {
            const int j = (tid >> 4) + 16 * it;
            const int c0 = eqc * 4;
            float4 vv = *(const float4*)(vbase + (size_t)(s0 + j) * DMODEL + c0);
            const int off = swz((j & 3) * 32 + (j >> 2));
            v_s[(c0 + 0) * VSTR + off] = f2tf(vv.x);
            v_s[(c0 + 1) * VSTR + off] = f2tf(vv.y);
            v_s[(c0 + 2) * VSTR + off] = f2tf(vv.z);
            v_s[(c0 + 3) * VSTR + off] = f2tf(vv.w);
        }
        __syncthreads();

        float sc[16][4];
        #pragma unroll
        for (int nt = 0; nt < 16; nt++)
            #pragma unroll
            for (int f = 0; f < 4; f++) sc[nt][f] = 0.0f;

        #pragma unroll
        for (int nt = 0; nt < 16; nt++) {
            uint32_t kb[16];
            const uint32_t* kp = k_s + (nt * 8 + g) * KSTR;
            #pragma unroll
            for (int u = 0; u < 4; u++)
                *(uint4*)&kb[u * 4] = *(const uint4*)&kp[fo16[u]];
            #pragma unroll
            for (int ks = 0; ks < 8; ks++)
                mma_tf32(sc[nt], qa[2 * ks], qb[2 * ks], qa[2 * ks + 1], qb[2 * ks + 1],
                         kb[2 * ks], kb[2 * ks + 1]);
        }

        float tm0 = -1e30f, tm1 = -1e30f;
        #pragma unroll
        for (int nt = 0; nt < 16; nt++) {
            tm0 = fmaxf(tm0, fmaxf(sc[nt][0], sc[nt][1]));
            tm1 = fmaxf(tm1, fmaxf(sc[nt][2], sc[nt][3]));
        }
        tm0 = fmaxf(tm0, __shfl_xor_sync(0xffffffffu, tm0, 1));
        tm0 = fmaxf(tm0, __shfl_xor_sync(0xffffffffu, tm0, 2));
        tm1 = fmaxf(tm1, __shfl_xor_sync(0xffffffffu, tm1, 1));
        tm1 = fmaxf(tm1, __shfl_xor_sync(0xffffffffu, tm1, 2));

        const float nm0 = fmaxf(m0, tm0);
        const float nm1 = fmaxf(m1, tm1);
        const float corr0 = __expf(m0 - nm0);
        const float corr1 = __expf(m1 - nm1);
        m0 = nm0; m1 = nm1;

        float rs0 = 0.0f, rs1 = 0.0f;
        #pragma unroll
        for (int nt = 0; nt < 16; nt++) {
            sc[nt][0] = __expf(sc[nt][0] - m0); rs0 += sc[nt][0];
            sc[nt][1] = __expf(sc[nt][1] - m0); rs0 += sc[nt][1];
            sc[nt][2] = __expf(sc[nt][2] - m1); rs1 += sc[nt][2];
            sc[nt][3] = __expf(sc[nt][3] - m1); rs1 += sc[nt][3];
        }
        rs0 += __shfl_xor_sync(0xffffffffu, rs0, 1);
        rs0 += __shfl_xor_sync(0xffffffffu, rs0, 2);
        rs1 += __shfl_xor_sync(0xffffffffu, rs1, 1);
        rs1 += __shfl_xor_sync(0xffffffffu, rs1, 2);
        l0 = l0 * corr0 + rs0;
        l1 = l1 * corr1 + rs1;

        #pragma unroll
        for (int nt = 0; nt < 8; nt++) {
            av[nt][0] *= corr0; av[nt][1] *= corr0;
            av[nt][2] *= corr1; av[nt][3] *= corr1;
        }

        #pragma unroll
        for (int nt = 0; nt < 16; nt++) {
            const int o0 = swz(pj0 + 2 * nt);
            const int o1 = swz(pj1 + 2 * nt);
            p_s[(qrow + g) * PSTR + o0]     = f2tf(sc[nt][0]);
            p_s[(qrow + g) * PSTR + o1]     = f2tf(sc[nt][1]);
            p_s[(qrow + g + 8) * PSTR + o0] = f2tf(sc[nt][2]);
            p_s[(qrow + g + 8) * PSTR + o1] = f2tf(sc[nt][3]);
        }
        __syncthreads();

        uint32_t pa[32], pb[32];
        {
            const uint32_t* r0 = p_s + (qrow + g) * PSTR;
            const uint32_t* r1 = p_s + (qrow + g + 8) * PSTR;
            #pragma unroll
            for (int u = 0; u < 8; u++) {
                *(uint4*)&pa[u * 4] = *(const uint4*)&r0[fo32[u]];
                *(uint4*)&pb[u * 4] = *(const uint4*)&r1[fo32[u]];
            }
        }
        #pragma unroll
        for (int nt = 0; nt < 8; nt++) {
            uint32_t vb[32];
            const uint32_t* vp = v_s + (nt * 8 + g) * VSTR;
            #pragma unroll
            for (int u = 0; u < 8; u++)
                *(uint4*)&vb[u * 4] = *(const uint4*)&vp[fo32[u]];
            #pragma unroll
            for (int ks = 0; ks < 16; ks++)
                mma_tf32(av[nt], pa[2 * ks], pb[2 * ks], pa[2 * ks + 1], pb[2 * ks + 1],
                         vb[2 * ks], vb[2 * ks + 1]);
        }
    }

    const float inv0 = 1.0f / l0;
    const float inv1 = 1.0f / l1;
    #pragma unroll
    for (int nt = 0; nt < 8; nt++) {
        const int c = nt * 8 + t * 2;
        float* o0 = go + (size_t)(b * LSEQ + q0 + qrow + g) * DMODEL + h * EDIM + c;
        float* o1 = go + (size_t)(b * LSEQ + q0 + qrow + g + 8) * DMODEL + h * EDIM + c;
        *(float2*)o0 = make_float2(av[nt][0] * inv0, av[nt][1] * inv0);
        *(float2*)o1 = make_float2(av[nt][2] * inv1, av[nt][3] * inv1);
    }
}

// ---------------------------------------------------------------------------
// launch
// ---------------------------------------------------------------------------
extern "C" void kernel_launch(void* const* d_in, const int* in_sizes, int n_in,
                              void* d_out, int out_size)
{
    (void)in_sizes; (void)n_in; (void)out_size;
    const float* queries = (const float*)d_in[0];
    const float* keys    = (const float*)d_in[1];
    const float* values  = (const float*)d_in[2];
    const float* Wq = (const float*)d_in[3];
    const float* bq = (const float*)d_in[4];
    const float* Wk = (const float*)d_in[5];
    const float* bk = (const float*)d_in[6];
    const float* Wv = (const float*)d_in[7];
    const float* bv = (const float*)d_in[8];
    const float* Wo = (const float*)d_in[9];
    const float* bo = (const float*)d_in[10];
    float* out = (float*)d_out;

    float *q, *k, *v, *attn, *wq, *wk, *wv, *wo;
    cudaGetSymbolAddress((void**)&q,    g_q);
    cudaGetSymbolAddress((void**)&k,    g_k);
    cudaGetSymbolAddress((void**)&v,    g_v);
    cudaGetSymbolAddress((void**)&attn, g_attn);
    cudaGetSymbolAddress((void**)&wq,   g_wq);
    cudaGetSymbolAddress((void**)&wk,   g_wk);
    cudaGetSymbolAddress((void**)&wv,   g_wv);
    cudaGetSymbolAddress((void**)&wo,   g_wo);

    cudaFuncSetAttribute(gemm_tf32_kernel,
                         cudaFuncAttributeMaxDynamicSharedMemorySize,
                         GEMM_SMEM_BYTES);
    cudaFuncSetAttribute(attn_mma_kernel,
                         cudaFuncAttributeMaxDynamicSharedMemorySize,
                         ATTN_SMEM_BYTES);

    // 1. pre-convert weights to tf32
    WC wc;
    wc.src[0] = Wq; wc.src[1] = Wk; wc.src[2] = Wv; wc.src[3] = Wo;
    wc.dst[0] = wq; wc.dst[1] = wk; wc.dst[2] = wv; wc.dst[3] = wo;
    wconv_kernel<<<dim3(DMODEL * DMODEL / (256 * 4), 4), 256>>>(wc);

    // 2. QKV projections (batched)
    G3 pq;
    pq.A[0] = queries; pq.A[1] = keys; pq.A[2] = values;
    pq.W[0] = wq;      pq.W[1] = wk;   pq.W[2] = wv;
    pq.B[0] = bq;      pq.B[1] = bk;   pq.B[2] = bv;
    pq.C[0] = q;       pq.C[1] = k;    pq.C[2] = v;
    gemm_tf32_kernel<<<dim3(GEMM_N / 128, MTOT / 128, 3), 256, GEMM_SMEM_BYTES>>>(pq);

    // 3. attention
    attn_mma_kernel<<<dim3(LSEQ / 128, BATCH * NHEAD), 256, ATTN_SMEM_BYTES>>>(q, k, v, attn);

    // 4. output projection
    G3 po;
    po.A[0] = attn; po.W[0] = wo; po.B[0] = bo; po.C[0] = out;
    po.A[1] = po.A[2] = attn; po.W[1] = po.W[2] = wo;
    po.B[1] = po.B[2] = bo;   po.C[1] = po.C[2] = out;
    gemm_tf32_kernel<<<dim3(GEMM_N / 128, MTOT / 128, 1), 256, GEMM_SMEM_BYTES>>>(po);
}

// round 11
// speedup vs baseline: 1.7293x; 1.7293x over previous
#include <cuda_runtime.h>
#include <cuda_fp16.h>
#include <math.h>
#include <stdint.h>

#define BATCH 4
#define LSEQ  2048
#define SSEQ  2048
#define DMODEL 1024
#define NHEAD 16
#define EDIM  64
#define MTOT  (BATCH * LSEQ)

__device__ __forceinline__ void mma_f16(float d[4], uint32_t a0, uint32_t a1,
                                        uint32_t a2, uint32_t a3,
                                        uint32_t b0, uint32_t b1) {
    asm volatile(
        "mma.sync.aligned.m16n8k16.row.col.f32.f16.f16.f32 "
        "{%0,%1,%2,%3}, {%4,%5,%6,%7}, {%8,%9}, {%0,%1,%2,%3};"
        : "+f"(d[0]), "+f"(d[1]), "+f"(d[2]), "+f"(d[3])
        : "r"(a0), "r"(a1), "r"(a2), "r"(a3), "r"(b0), "r"(b1));
}
__device__ __forceinline__ uint32_t smem_u32(const void* p) {
    uint32_t a;
    asm("{ .reg .u64 t; cvta.to.shared.u64 t, %1; cvt.u32.u64 %0, t; }" : "=r"(a) : "l"(p));
    return a;
}
__device__ __forceinline__ void cpa16(uint32_t dst, const void* src) {
    asm volatile("cp.async.cg.shared.global [%0], [%1], 16;" :: "r"(dst), "l"(src));
}
__device__ __forceinline__ void cpa_commit() { asm volatile("cp.async.commit_group;" ::: "memory"); }
__device__ __forceinline__ void cpa_wait2() { asm volatile("cp.async.wait_group 2;" ::: "memory"); }
__device__ __forceinline__ void cpa_wait1() { asm volatile("cp.async.wait_group 1;" ::: "memory"); }
__device__ __forceinline__ void cpa_wait0() { asm volatile("cp.async.wait_group 0;" ::: "memory"); }
__device__ __forceinline__ uint32_t ldh2(const __half* p) { return *(const uint32_t*)p; }

// scratch
__device__ __align__(16) __half g_inq[MTOT * DMODEL];
__device__ __align__(16) __half g_ink[MTOT * DMODEL];
__device__ __align__(16) __half g_inv[MTOT * DMODEL];
__device__ __align__(16) __half g_qh[MTOT * DMODEL];
__device__ __align__(16) __half g_kh[MTOT * DMODEL];
__device__ __align__(16) __half g_vT[MTOT * DMODEL];   // [b*1024+n][s]
__device__ __align__(16) __half g_ah[MTOT * DMODEL];
__device__ __align__(16) __half g_whq[DMODEL * DMODEL]; // W^T [n][k]
__device__ __align__(16) __half g_whk[DMODEL * DMODEL];
__device__ __align__(16) __half g_whv[DMODEL * DMODEL];
__device__ __align__(16) __half g_who[DMODEL * DMODEL];

// weights: fp32 [k][n] -> half [n][k] (+scale)
struct WC4 { const float* src[4]; __half* dst[4]; float scale[4]; };
__global__ __launch_bounds__(256) void wconv_kernel(WC4 p) {
    __shared__ float tile[32][33];
    const int z = blockIdx.z;
    const float* S = p.src[z];
    __half* D = p.dst[z];
    const float sc = p.scale[z];
    const int k0 = blockIdx.y * 32, n0 = blockIdx.x * 32;
    const int tx = threadIdx.x, ty = threadIdx.y;
    #pragma unroll
    for (int i = 0; i < 4; i++)
        tile[ty + 8 * i][tx] = S[(size_t)(k0 + ty + 8 * i) * DMODEL + n0 + tx];
    __syncthreads();
    #pragma unroll
    for (int i = 0; i < 4; i++)
        D[(size_t)(n0 + ty + 8 * i) * DMODEL + k0 + tx] =
            __float2half(tile[tx][ty + 8 * i] * sc);
}

// activations fp32 -> half
struct AC3 { const float* src[3]; __half* dst[3]; };
__global__ __launch_bounds__(256) void aconv_kernel(AC3 p) {
    const int z = blockIdx.y;
    const float4* s = (const float4*)p.src[z];
    __half* d = p.dst[z];
    const size_t i = (size_t)blockIdx.x * 256 + threadIdx.x;
    float4 v0 = s[i * 2], v1 = s[i * 2 + 1];
    __half2 h[4];
    h[0] = __floats2half2_rn(v0.x, v0.y);
    h[1] = __floats2half2_rn(v0.z, v0.w);
    h[2] = __floats2half2_rn(v1.x, v1.y);
    h[3] = __floats2half2_rn(v1.z, v1.w);
    *(uint4*)(d + i * 8) = *(uint4*)h;
}

// f16 GEMM: C = Ah[m][k] @ Wh[n][k]^T + bias*bscale. 128x128, BK=32, 4-stage.
#define SA_STR 40
#define STG_H (128 * SA_STR)
#define GSM_BYTES (8 * STG_H * 2)
#define NSTG 32

struct G4 {
    const __half* A[3]; const __half* W[3]; const float* bias[3];
    float bscale[3]; __half* Ch[3]; float* Cf[3]; int mode[3];
};

__global__ __launch_bounds__(256, 2) void gemm_f16_kernel(G4 p) {
    extern __shared__ __half hsm[];
    const int z = blockIdx.z;
    const __half* __restrict__ A = p.A[z];
    const __half* __restrict__ W = p.W[z];
    const float* __restrict__ bias = p.bias[z];

    const int tid = threadIdx.x;
    const int wid = tid >> 5, lane = tid & 31;
    const int g = lane >> 2, t = lane & 3;
    const int m_base = blockIdx.y * 128, n_base = blockIdx.x * 128;
    const int warp_m = (wid & 3) * 32, warp_n = (wid >> 2) * 64;

    const int r0 = tid >> 1;
    const int c0 = (tid & 1) * 2;
    const uint32_t smb = smem_u32(hsm);
    const __half* Asrc = A + (size_t)(m_base + r0) * DMODEL;
    const __half* Bsrc = W + (size_t)(n_base + r0) * DMODEL;

    float acc[2][8][4];
    #pragma unroll
    for (int ma = 0; ma < 2; ma++)
        #pragma unroll
        for (int na = 0; na < 8; na++)
            #pragma unroll
            for (int f = 0; f < 4; f++) acc[ma][na][f] = 0.0f;

    #define GISSUE(s)                                                          \
        do {                                                                   \
            const int k0_ = (s) * 32;                                          \
            const int sb_ = (s) & 3;                                           \
            const uint32_t ab = smb + (sb_ * STG_H + r0 * SA_STR) * 2;         \
            const uint32_t bb = smb + ((4 + sb_) * STG_H + r0 * SA_STR) * 2;   \
            cpa16(ab + c0 * 16,       Asrc + k0_ + c0 * 8);                    \
            cpa16(ab + (c0 + 1) * 16, Asrc + k0_ + (c0 + 1) * 8);              \
            cpa16(bb + c0 * 16,       Bsrc + k0_ + c0 * 8);                    \
            cpa16(bb + (c0 + 1) * 16, Bsrc + k0_ + (c0 + 1) * 8);              \
            cpa_commit();                                                      \
        } while (0)

    GISSUE(0); GISSUE(1); GISSUE(2);

    for (int s = 0; s < NSTG; s++) {
        if (s < NSTG - 2) cpa_wait2();
        else if (s == NSTG - 2) cpa_wait1();
        else cpa_wait0();
        __syncthreads();
        if (s + 3 < NSTG) GISSUE(s + 3);

        const __half* As = hsm + (s & 3) * STG_H;
        const __half* Bs = hsm + (4 + (s & 3)) * STG_H;

        #pragma unroll
        for (int ks = 0; ks < 2; ks++) {
            uint32_t af[2][4];
            #pragma unroll
            for (int ma = 0; ma < 2; ma++) {
                const __half* ap = As + (warp_m + ma * 16 + g) * SA_STR + 16 * ks + 2 * t;
                af[ma][0] = ldh2(ap);
                af[ma][1] = ldh2(ap + 8 * SA_STR);
                af[ma][2] = ldh2(ap + 8);
                af[ma][3] = ldh2(ap + 8 * SA_STR + 8);
            }
            #pragma unroll
            for (int na = 0; na < 8; na++) {
                const __half* bp = Bs + (warp_n + na * 8 + g) * SA_STR + 16 * ks + 2 * t;
                const uint32_t b0 = ldh2(bp);
                const uint32_t b1 = ldh2(bp + 8);
                mma_f16(acc[0][na], af[0][0], af[0][1], af[0][2], af[0][3], b0, b1);
                mma_f16(acc[1][na], af[1][0], af[1][1], af[1][2], af[1][3], b0, b1);
            }
        }
        __syncthreads();
    }
    #undef GISSUE

    const int mode = p.mode[z];
    const float bs = p.bscale[z];
    #pragma unroll
    for (int na = 0; na < 8; na++) {
        const int col = n_base + warp_n + na * 8 + t * 2;
        const float bx = __ldg(bias + col) * bs;
        const float by = __ldg(bias + col + 1) * bs;
        #pragma unroll
        for (int ma = 0; ma < 2; ma++) {
            const int rm = m_base + warp_m + ma * 16 + g;
            const float v0 = acc[ma][na][0] + bx, v1 = acc[ma][na][1] + by;
            const float v2 = acc[ma][na][2] + bx, v3 = acc[ma][na][3] + by;
            if (mode == 2) {
                float* Cf = p.Cf[z];
                *(float2*)(Cf + (size_t)rm * DMODEL + col)       = make_float2(v0, v1);
                *(float2*)(Cf + (size_t)(rm + 8) * DMODEL + col) = make_float2(v2, v3);
            } else if (mode == 0) {
                __half* Ch = p.Ch[z];
                *(__half2*)(Ch + (size_t)rm * DMODEL + col)       = __floats2half2_rn(v0, v1);
                *(__half2*)(Ch + (size_t)(rm + 8) * DMODEL + col) = __floats2half2_rn(v2, v3);
            } else {
                __half* Ch = p.Ch[z];
                const int bi = rm >> 11, srow = rm & 2047;
                Ch[((size_t)bi * 1024 + col) * 2048 + srow]         = __float2half(v0);
                Ch[((size_t)bi * 1024 + col + 1) * 2048 + srow]     = __float2half(v1);
                Ch[((size_t)bi * 1024 + col) * 2048 + srow + 8]     = __float2half(v2);
                Ch[((size_t)bi * 1024 + col + 1) * 2048 + srow + 8] = __float2half(v3);
            }
        }
    }
}

// f16 flash attention: 128q x 128S per CTA, 8 warps. cp.async staging only.
#define PS_STR 136
#define KS_STR 72
#define VS_STR 136
#define PS_OFF_H 0
#define KS_OFF_H 17408
#define VS_OFF_H 26624
#define ATTN_SMEM_BYTES ((26624 + 64 * VS_STR) * 2)

__global__ __launch_bounds__(256, 1) void attn_f16_kernel(
    const __half* __restrict__ gq, const __half* __restrict__ gk,
    const __half* __restrict__ gvT, __half* __restrict__ go)
{
    extern __shared__ __half hsm[];
    __half* Ps = hsm + PS_OFF_H;
    __half* Ks = hsm + KS_OFF_H;
    __half* Vs = hsm + VS_OFF_H;

    const int bh = blockIdx.y;
    const int b = bh >> 4, h = bh & 15;
    const int q0 = blockIdx.x * 128;
    const int tid = threadIdx.x;
    const int wid = tid >> 5, lane = tid & 31;
    const int g = lane >> 2, t = lane & 3;
    const int qrow = wid * 16;

    const __half* qbase = gq + (size_t)(b * LSEQ + q0) * DMODEL + h * EDIM;
    const __half* kbase = gk + (size_t)b * SSEQ * DMODEL + h * EDIM;
    const __half* vbase = gvT + ((size_t)b * 1024 + h * EDIM) * 2048;
    const uint32_t smb = smem_u32(hsm);

    // stage Q
    #pragma unroll
    for (int i = 0; i < 4; i++) {
        const int qd = tid + 256 * i;
        const int r = qd >> 3, co = qd & 7;
        cpa16(smb + (PS_OFF_H + r * PS_STR + co * 8) * 2,
              qbase + (size_t)r * DMODEL + co * 8);
    }
    cpa_commit(); cpa_wait0();
    __syncthreads();

    uint32_t qa[4][4];
    #pragma unroll
    for (int ks = 0; ks < 4; ks++) {
        const __half* qp = Ps + (qrow + g) * PS_STR + 16 * ks + 2 * t;
        qa[ks][0] = ldh2(qp);
        qa[ks][1] = ldh2(qp + 8 * PS_STR);
        qa[ks][2] = ldh2(qp + 8);
        qa[ks][3] = ldh2(qp + 8 * PS_STR + 8);
    }

    float m0 = -1e30f, m1 = -1e30f, l0 = 0.0f, l1 = 0.0f;
    float av[8][4];
    #pragma unroll
    for (int ct = 0; ct < 8; ct++)
        #pragma unroll
        for (int f = 0; f < 4; f++) av[ct][f] = 0.0f;

    for (int s0 = 0; s0 < SSEQ; s0 += 128) {
        __syncthreads();
        #pragma unroll
        for (int i = 0; i < 4; i++) {
            const int qd = tid + 256 * i;
            const int r = qd >> 3, co = qd & 7;
            cpa16(smb + (KS_OFF_H + r * KS_STR + co * 8) * 2,
                  kbase + (size_t)(s0 + r) * DMODEL + co * 8);
        }
        #pragma unroll
        for (int i = 0; i < 4; i++) {
            const int qd = tid + 256 * i;
            const int c = qd >> 4, co = qd & 15;
            cpa16(smb + (VS_OFF_H + c * VS_STR + co * 8) * 2,
                  vbase + (size_t)c * 2048 + s0 + co * 8);
        }
        cpa_commit(); cpa_wait0();
        __syncthreads();

        float sc[16][4];
        #pragma unroll
        for (int nt = 0; nt < 16; nt++)
            #pragma unroll
            for (int f = 0; f < 4; f++) sc[nt][f] = 0.0f;

        #pragma unroll
        for (int nt = 0; nt < 16; nt++) {
            const __half* kp = Ks + (nt * 8 + g) * KS_STR + 2 * t;
            #pragma unroll
            for (int ks = 0; ks < 4; ks++) {
                const uint32_t b0 = ldh2(kp + 16 * ks);
                const uint32_t b1 = ldh2(kp + 16 * ks + 8);
                mma_f16(sc[nt], qa[ks][0], qa[ks][1], qa[ks][2], qa[ks][3], b0, b1);
            }
        }

        float tm0 = -1e30f, tm1 = -1e30f;
        #pragma unroll
        for (int nt = 0; nt < 16; nt++) {
            tm0 = fmaxf(tm0, fmaxf(sc[nt][0], sc[nt][1]));
            tm1 = fmaxf(tm1, fmaxf(sc[nt][2], sc[nt][3]));
        }
        tm0 = fmaxf(tm0, __shfl_xor_sync(0xffffffffu, tm0, 1));
        tm0 = fmaxf(tm0, __shfl_xor_sync(0xffffffffu, tm0, 2));
        tm1 = fmaxf(tm1, __shfl_xor_sync(0xffffffffu, tm1, 1));
        tm1 = fmaxf(tm1, __shfl_xor_sync(0xffffffffu, tm1, 2));
        const float nm0 = fmaxf(m0, tm0);
        const float nm1 = fmaxf(m1, tm1);
        const float corr0 = __expf(m0 - nm0);
        const float corr1 = __expf(m1 - nm1);
        m0 = nm0; m1 = nm1;

        float rs0 = 0.0f, rs1 = 0.0f;
        #pragma unroll
        for (int nt = 0; nt < 16; nt++) {
            sc[nt][0] = __expf(sc[nt][0] - m0); rs0 += sc[nt][0];
            sc[nt][1] = __expf(sc[nt][1] - m0); rs0 += sc[nt][1];
            sc[nt][2] = __expf(sc[nt][2] - m1); rs1 += sc[nt][2];
            sc[nt][3] = __expf(sc[nt][3] - m1); rs1 += sc[nt][3];
        }
        rs0 += __shfl_xor_sync(0xffffffffu, rs0, 1);
        rs0 += __shfl_xor_sync(0xffffffffu, rs0, 2);
        rs1 += __shfl_xor_sync(0xffffffffu, rs1, 1);
        rs1 += __shfl_xor_sync(0xffffffffu, rs1, 2);
        l0 = l0 * corr0 + rs0;
        l1 = l1 * corr1 + rs1;

        #pragma unroll
        for (int ct = 0; ct < 8; ct++) {
            av[ct][0] *= corr0; av[ct][1] *= corr0;
            av[ct][2] *= corr1; av[ct][3] *= corr1;
        }

        // P -> half into Ps (warp-private rows)
        #pragma unroll
        for (int nt = 0; nt < 16; nt++) {
            *(__half2*)(Ps + (qrow + g) * PS_STR + nt * 8 + 2 * t) =
                __floats2half2_rn(sc[nt][0], sc[nt][1]);
            *(__half2*)(Ps + (qrow + g + 8) * PS_STR + nt * 8 + 2 * t) =
                __floats2half2_rn(sc[nt][2], sc[nt][3]);
        }
        __syncwarp();

        uint32_t pa[8][4];
        #pragma unroll
        for (int ks = 0; ks < 8; ks++) {
            const __half* pp = Ps + (qrow + g) * PS_STR + 16 * ks + 2 * t;
            pa[ks][0] = ldh2(pp);
            pa[ks][1] = ldh2(pp + 8 * PS_STR);
            pa[ks][2] = ldh2(pp + 8);
            pa[ks][3] = ldh2(pp + 8 * PS_STR + 8);
        }
        #pragma unroll
        for (int ct = 0; ct < 8; ct++) {
            const __half* vp = Vs + (ct * 8 + g) * VS_STR + 2 * t;
            #pragma unroll
            for (int ks = 0; ks < 8; ks++) {
                const uint32_t b0 = ldh2(vp + 16 * ks);
                const uint32_t b1 = ldh2(vp + 16 * ks + 8);
                mma_f16(av[ct], pa[ks][0], pa[ks][1], pa[ks][2], pa[ks][3], b0, b1);
            }
        }
    }

    const float inv0 = 1.0f / l0;
    const float inv1 = 1.0f / l1;
    #pragma unroll
    for (int ct = 0; ct < 8; ct++) {
        const int col = h * EDIM + ct * 8 + 2 * t;
        __half* o0 = go + (size_t)(b * LSEQ + q0 + qrow + g) * DMODEL + col;
        __half* o1 = go + (size_t)(b * LSEQ + q0 + qrow + g + 8) * DMODEL + col;
        *(__half2*)o0 = __floats2half2_rn(av[ct][0] * inv0, av[ct][1] * inv0);
        *(__half2*)o1 = __floats2half2_rn(av[ct][2] * inv1, av[ct][3] * inv1);
    }
}

extern "C" void kernel_launch(void* const* d_in, const int* in_sizes, int n_in,
                              void* d_out, int out_size)
{
    (void)in_sizes; (void)n_in; (void)out_size;
    const float* queries = (const float*)d_in[0];
    const float* keys    = (const float*)d_in[1];
    const float* values  = (const float*)d_in[2];
    const float* Wq = (const float*)d_in[3];
    const float* bq = (const float*)d_in[4];
    const float* Wk = (const float*)d_in[5];
    const float* bk = (const float*)d_in[6];
    const float* Wv = (const float*)d_in[7];
    const float* bv = (const float*)d_in[8];
    const float* Wo = (const float*)d_in[9];
    const float* bo = (const float*)d_in[10];
    float* out = (float*)d_out;

    __half *inq, *ink, *inv, *qh, *kh, *vT, *ah, *whq, *whk, *whv, *who;
    cudaGetSymbolAddress((void**)&inq, g_inq);
    cudaGetSymbolAddress((void**)&ink, g_ink);
    cudaGetSymbolAddress((void**)&inv, g_inv);
    cudaGetSymbolAddress((void**)&qh,  g_qh);
    cudaGetSymbolAddress((void**)&kh,  g_kh);
    cudaGetSymbolAddress((void**)&vT,  g_vT);
    cudaGetSymbolAddress((void**)&ah,  g_ah);
    cudaGetSymbolAddress((void**)&whq, g_whq);
    cudaGetSymbolAddress((void**)&whk, g_whk);
    cudaGetSymbolAddress((void**)&whv, g_whv);
    cudaGetSymbolAddress((void**)&who, g_who);

    cudaFuncSetAttribute(gemm_f16_kernel,
                         cudaFuncAttributeMaxDynamicSharedMemorySize, GSM_BYTES);
    cudaFuncSetAttribute(attn_f16_kernel,
                         cudaFuncAttributeMaxDynamicSharedMemorySize, ATTN_SMEM_BYTES);

    WC4 wc;
    wc.src[0] = Wq;  wc.src[1] = Wk;  wc.src[2] = Wv;  wc.src[3] = Wo;
    wc.dst[0] = whq; wc.dst[1] = whk; wc.dst[2] = whv; wc.dst[3] = who;
    wc.scale[0] = 0.125f; wc.scale[1] = 1.0f; wc.scale[2] = 1.0f; wc.scale[3] = 1.0f;
    wconv_kernel<<<dim3(32, 32, 4), dim3(32, 8)>>>(wc);

    AC3 ac;
    ac.src[0] = queries; ac.src[1] = keys; ac.src[2] = values;
    ac.dst[0] = inq;     ac.dst[1] = ink;  ac.dst[2] = inv;
    aconv_kernel<<<dim3(MTOT * DMODEL / (256 * 8), 3), 256>>>(ac);

    G4 pq;
    pq.A[0] = inq; pq.A[1] = ink; pq.A[2] = inv;
    pq.W[0] = whq; pq.W[1] = whk; pq.W[2] = whv;
    pq.bias[0] = bq; pq.bias[1] = bk; pq.bias[2] = bv;
    pq.bscale[0] = 0.125f; pq.bscale[1] = 1.0f; pq.bscale[2] = 1.0f;
    pq.Ch[0] = qh; pq.Ch[1] = kh; pq.Ch[2] = vT;
    pq.Cf[0] = pq.Cf[1] = pq.Cf[2] = nullptr;
    pq.mode[0] = 0; pq.mode[1] = 0; pq.mode[2] = 1;
    gemm_f16_kernel<<<dim3(8, 64, 3), 256, GSM_BYTES>>>(pq);

    attn_f16_kernel<<<dim3(LSEQ / 128, BATCH * NHEAD), 256, ATTN_SMEM_BYTES>>>(
        qh, kh, vT, ah);

    G4 po;
    po.A[0] = po.A[1] = po.A[2] = ah;
    po.W[0] = po.W[1] = po.W[2] = who;
    po.bias[0] = po.bias[1] = po.bias[2] = bo;
    po.bscale[0] = po.bscale[1] = po.bscale[2] = 1.0f;
    po.Ch[0] = po.Ch[1] = po.Ch[2] = nullptr;
    po.Cf[0] = po.Cf[1] = po.Cf[2] = out;
    po.mode[0] = po.mode[1] = po.mode[2] = 2;
    gemm_f16_kernel<<<dim3(8, 64, 1), 256, GSM_BYTES>>>(po);
}

// round 12
// speedup vs baseline: 1.8250x; 1.0553x over previous
#include <cuda_runtime.h>
#include <cuda_fp16.h>
#include <math.h>
#include <stdint.h>

// R12: R11 + double-buffered K/V cp.async pipeline in attention (overlap
// tile s+1 load with tile s compute). GEMMs/convs unchanged from R11.

#define BATCH 4
#define LSEQ  2048
#define SSEQ  2048
#define DMODEL 1024
#define NHEAD 16
#define EDIM  64
#define MTOT  (BATCH * LSEQ)

__device__ __forceinline__ void mma_f16(float d[4], uint32_t a0, uint32_t a1,
                                        uint32_t a2, uint32_t a3,
                                        uint32_t b0, uint32_t b1) {
    asm volatile(
        "mma.sync.aligned.m16n8k16.row.col.f32.f16.f16.f32 "
        "{%0,%1,%2,%3}, {%4,%5,%6,%7}, {%8,%9}, {%0,%1,%2,%3};"
        : "+f"(d[0]), "+f"(d[1]), "+f"(d[2]), "+f"(d[3])
        : "r"(a0), "r"(a1), "r"(a2), "r"(a3), "r"(b0), "r"(b1));
}
__device__ __forceinline__ uint32_t smem_u32(const void* p) {
    uint32_t a;
    asm("{ .reg .u64 t; cvta.to.shared.u64 t, %1; cvt.u32.u64 %0, t; }" : "=r"(a) : "l"(p));
    return a;
}
__device__ __forceinline__ void cpa16(uint32_t dst, const void* src) {
    asm volatile("cp.async.cg.shared.global [%0], [%1], 16;" :: "r"(dst), "l"(src));
}
__device__ __forceinline__ void cpa_commit() { asm volatile("cp.async.commit_group;" ::: "memory"); }
__device__ __forceinline__ void cpa_wait2() { asm volatile("cp.async.wait_group 2;" ::: "memory"); }
__device__ __forceinline__ void cpa_wait1() { asm volatile("cp.async.wait_group 1;" ::: "memory"); }
__device__ __forceinline__ void cpa_wait0() { asm volatile("cp.async.wait_group 0;" ::: "memory"); }
__device__ __forceinline__ uint32_t ldh2(const __half* p) { return *(const uint32_t*)p; }

// scratch
__device__ __align__(16) __half g_inq[MTOT * DMODEL];
__device__ __align__(16) __half g_ink[MTOT * DMODEL];
__device__ __align__(16) __half g_inv[MTOT * DMODEL];
__device__ __align__(16) __half g_qh[MTOT * DMODEL];
__device__ __align__(16) __half g_kh[MTOT * DMODEL];
__device__ __align__(16) __half g_vT[MTOT * DMODEL];   // [b*1024+n][s]
__device__ __align__(16) __half g_ah[MTOT * DMODEL];
__device__ __align__(16) __half g_whq[DMODEL * DMODEL]; // W^T [n][k]
__device__ __align__(16) __half g_whk[DMODEL * DMODEL];
__device__ __align__(16) __half g_whv[DMODEL * DMODEL];
__device__ __align__(16) __half g_who[DMODEL * DMODEL];

// weights: fp32 [k][n] -> half [n][k] (+scale)
struct WC4 { const float* src[4]; __half* dst[4]; float scale[4]; };
__global__ __launch_bounds__(256) void wconv_kernel(WC4 p) {
    __shared__ float tile[32][33];
    const int z = blockIdx.z;
    const float* S = p.src[z];
    __half* D = p.dst[z];
    const float sc = p.scale[z];
    const int k0 = blockIdx.y * 32, n0 = blockIdx.x * 32;
    const int tx = threadIdx.x, ty = threadIdx.y;
    #pragma unroll
    for (int i = 0; i < 4; i++)
        tile[ty + 8 * i][tx] = S[(size_t)(k0 + ty + 8 * i) * DMODEL + n0 + tx];
    __syncthreads();
    #pragma unroll
    for (int i = 0; i < 4; i++)
        D[(size_t)(n0 + ty + 8 * i) * DMODEL + k0 + tx] =
            __float2half(tile[tx][ty + 8 * i] * sc);
}

// activations fp32 -> half
struct AC3 { const float* src[3]; __half* dst[3]; };
__global__ __launch_bounds__(256) void aconv_kernel(AC3 p) {
    const int z = blockIdx.y;
    const float4* s = (const float4*)p.src[z];
    __half* d = p.dst[z];
    const size_t i = (size_t)blockIdx.x * 256 + threadIdx.x;
    float4 v0 = s[i * 2], v1 = s[i * 2 + 1];
    __half2 h[4];
    h[0] = __floats2half2_rn(v0.x, v0.y);
    h[1] = __floats2half2_rn(v0.z, v0.w);
    h[2] = __floats2half2_rn(v1.x, v1.y);
    h[3] = __floats2half2_rn(v1.z, v1.w);
    *(uint4*)(d + i * 8) = *(uint4*)h;
}

// f16 GEMM (unchanged from R11): C = Ah @ Wh^T + bias*bscale. 128x128, BK=32.
#define SA_STR 40
#define STG_H (128 * SA_STR)
#define GSM_BYTES (8 * STG_H * 2)
#define NSTG 32

struct G4 {
    const __half* A[3]; const __half* W[3]; const float* bias[3];
    float bscale[3]; __half* Ch[3]; float* Cf[3]; int mode[3];
};

__global__ __launch_bounds__(256, 2) void gemm_f16_kernel(G4 p) {
    extern __shared__ __half hsm[];
    const int z = blockIdx.z;
    const __half* __restrict__ A = p.A[z];
    const __half* __restrict__ W = p.W[z];
    const float* __restrict__ bias = p.bias[z];

    const int tid = threadIdx.x;
    const int wid = tid >> 5, lane = tid & 31;
    const int g = lane >> 2, t = lane & 3;
    const int m_base = blockIdx.y * 128, n_base = blockIdx.x * 128;
    const int warp_m = (wid & 3) * 32, warp_n = (wid >> 2) * 64;

    const int r0 = tid >> 1;
    const int c0 = (tid & 1) * 2;
    const uint32_t smb = smem_u32(hsm);
    const __half* Asrc = A + (size_t)(m_base + r0) * DMODEL;
    const __half* Bsrc = W + (size_t)(n_base + r0) * DMODEL;

    float acc[2][8][4];
    #pragma unroll
    for (int ma = 0; ma < 2; ma++)
        #pragma unroll
        for (int na = 0; na < 8; na++)
            #pragma unroll
            for (int f = 0; f < 4; f++) acc[ma][na][f] = 0.0f;

    #define GISSUE(s)                                                          \
        do {                                                                   \
            const int k0_ = (s) * 32;                                          \
            const int sb_ = (s) & 3;                                           \
            const uint32_t ab = smb + (sb_ * STG_H + r0 * SA_STR) * 2;         \
            const uint32_t bb = smb + ((4 + sb_) * STG_H + r0 * SA_STR) * 2;   \
            cpa16(ab + c0 * 16,       Asrc + k0_ + c0 * 8);                    \
            cpa16(ab + (c0 + 1) * 16, Asrc + k0_ + (c0 + 1) * 8);              \
            cpa16(bb + c0 * 16,       Bsrc + k0_ + c0 * 8);                    \
            cpa16(bb + (c0 + 1) * 16, Bsrc + k0_ + (c0 + 1) * 8);              \
            cpa_commit();                                                      \
        } while (0)

    GISSUE(0); GISSUE(1); GISSUE(2);

    for (int s = 0; s < NSTG; s++) {
        if (s < NSTG - 2) cpa_wait2();
        else if (s == NSTG - 2) cpa_wait1();
        else cpa_wait0();
        __syncthreads();
        if (s + 3 < NSTG) GISSUE(s + 3);

        const __half* As = hsm + (s & 3) * STG_H;
        const __half* Bs = hsm + (4 + (s & 3)) * STG_H;

        #pragma unroll
        for (int ks = 0; ks < 2; ks++) {
            uint32_t af[2][4];
            #pragma unroll
            for (int ma = 0; ma < 2; ma++) {
                const __half* ap = As + (warp_m + ma * 16 + g) * SA_STR + 16 * ks + 2 * t;
                af[ma][0] = ldh2(ap);
                af[ma][1] = ldh2(ap + 8 * SA_STR);
                af[ma][2] = ldh2(ap + 8);
                af[ma][3] = ldh2(ap + 8 * SA_STR + 8);
            }
            #pragma unroll
            for (int na = 0; na < 8; na++) {
                const __half* bp = Bs + (warp_n + na * 8 + g) * SA_STR + 16 * ks + 2 * t;
                const uint32_t b0 = ldh2(bp);
                const uint32_t b1 = ldh2(bp + 8);
                mma_f16(acc[0][na], af[0][0], af[0][1], af[0][2], af[0][3], b0, b1);
                mma_f16(acc[1][na], af[1][0], af[1][1], af[1][2], af[1][3], b0, b1);
            }
        }
        __syncthreads();
    }
    #undef GISSUE

    const int mode = p.mode[z];
    const float bs = p.bscale[z];
    #pragma unroll
    for (int na = 0; na < 8; na++) {
        const int col = n_base + warp_n + na * 8 + t * 2;
        const float bx = __ldg(bias + col) * bs;
        const float by = __ldg(bias + col + 1) * bs;
        #pragma unroll
        for (int ma = 0; ma < 2; ma++) {
            const int rm = m_base + warp_m + ma * 16 + g;
            const float v0 = acc[ma][na][0] + bx, v1 = acc[ma][na][1] + by;
            const float v2 = acc[ma][na][2] + bx, v3 = acc[ma][na][3] + by;
            if (mode == 2) {
                float* Cf = p.Cf[z];
                *(float2*)(Cf + (size_t)rm * DMODEL + col)       = make_float2(v0, v1);
                *(float2*)(Cf + (size_t)(rm + 8) * DMODEL + col) = make_float2(v2, v3);
            } else if (mode == 0) {
                __half* Ch = p.Ch[z];
                *(__half2*)(Ch + (size_t)rm * DMODEL + col)       = __floats2half2_rn(v0, v1);
                *(__half2*)(Ch + (size_t)(rm + 8) * DMODEL + col) = __floats2half2_rn(v2, v3);
            } else {
                __half* Ch = p.Ch[z];
                const int bi = rm >> 11, srow = rm & 2047;
                Ch[((size_t)bi * 1024 + col) * 2048 + srow]         = __float2half(v0);
                Ch[((size_t)bi * 1024 + col + 1) * 2048 + srow]     = __float2half(v1);
                Ch[((size_t)bi * 1024 + col) * 2048 + srow + 8]     = __float2half(v2);
                Ch[((size_t)bi * 1024 + col + 1) * 2048 + srow + 8] = __float2half(v3);
            }
        }
    }
}

// f16 flash attention with double-buffered K/V cp.async pipeline.
#define PS_STR 136
#define KS_STR 72
#define VS_STR 136
#define PS_OFF_H  0
#define KS0_OFF_H 17408
#define KS1_OFF_H 26624
#define VS0_OFF_H 35840
#define VS1_OFF_H 44544
#define ATTN_SMEM_H 53248
#define ATTN_SMEM_BYTES (ATTN_SMEM_H * 2)
#define NS_TILES (SSEQ / 128)   // 16

__global__ __launch_bounds__(256, 1) void attn_f16_kernel(
    const __half* __restrict__ gq, const __half* __restrict__ gk,
    const __half* __restrict__ gvT, __half* __restrict__ go)
{
    extern __shared__ __half hsm[];
    __half* Ps = hsm + PS_OFF_H;

    const int bh = blockIdx.y;
    const int b = bh >> 4, h = bh & 15;
    const int q0 = blockIdx.x * 128;
    const int tid = threadIdx.x;
    const int wid = tid >> 5, lane = tid & 31;
    const int g = lane >> 2, t = lane & 3;
    const int qrow = wid * 16;

    const __half* qbase = gq + (size_t)(b * LSEQ + q0) * DMODEL + h * EDIM;
    const __half* kbase = gk + (size_t)b * SSEQ * DMODEL + h * EDIM;
    const __half* vbase = gvT + ((size_t)b * 1024 + h * EDIM) * 2048;
    const uint32_t smb = smem_u32(hsm);

    // per-thread staging coords (loop-invariant)
    const int kr = tid >> 3, kco = tid & 7;       // K: 32 rows/iter x 8 chunks
    const int vc = tid >> 4, vco = tid & 15;      // V: 16 cols/iter x 16 chunks

    #define KV_ISSUE(s, buf)                                                    \
        do {                                                                    \
            const int sb0_ = (s) * 128;                                         \
            const uint32_t ko_ = (buf) ? KS1_OFF_H : KS0_OFF_H;                 \
            const uint32_t vo_ = (buf) ? VS1_OFF_H : VS0_OFF_H;                 \
            _Pragma("unroll")                                                   \
            for (int i_ = 0; i_ < 4; i_++) {                                    \
                const int r_ = kr + 32 * i_;                                    \
                cpa16(smb + (ko_ + r_ * KS_STR + kco * 8) * 2,                  \
                      kbase + (size_t)(sb0_ + r_) * DMODEL + kco * 8);          \
            }                                                                   \
            _Pragma("unroll")                                                   \
            for (int i_ = 0; i_ < 4; i_++) {                                    \
                const int c_ = vc + 16 * i_;                                    \
                cpa16(smb + (vo_ + c_ * VS_STR + vco * 8) * 2,                  \
                      vbase + (size_t)c_ * 2048 + sb0_ + vco * 8);              \
            }                                                                   \
            cpa_commit();                                                       \
        } while (0)

    // prologue: stage Q (group) + KV tile 0 (group)
    #pragma unroll
    for (int i = 0; i < 4; i++) {
        const int qd = tid + 256 * i;
        const int r = qd >> 3, co = qd & 7;
        cpa16(smb + (PS_OFF_H + r * PS_STR + co * 8) * 2,
              qbase + (size_t)r * DMODEL + co * 8);
    }
    cpa_commit();
    KV_ISSUE(0, 0);
    cpa_wait0();
    __syncthreads();

    uint32_t qa[4][4];
    #pragma unroll
    for (int ks = 0; ks < 4; ks++) {
        const __half* qp = Ps + (qrow + g) * PS_STR + 16 * ks + 2 * t;
        qa[ks][0] = ldh2(qp);
        qa[ks][1] = ldh2(qp + 8 * PS_STR);
        qa[ks][2] = ldh2(qp + 8);
        qa[ks][3] = ldh2(qp + 8 * PS_STR + 8);
    }
    KV_ISSUE(1, 1);   // in flight during tile 0 compute

    float m0 = -1e30f, m1 = -1e30f, l0 = 0.0f, l1 = 0.0f;
    float av[8][4];
    #pragma unroll
    for (int ct = 0; ct < 8; ct++)
        #pragma unroll
        for (int f = 0; f < 4; f++) av[ct][f] = 0.0f;

    for (int s = 0; s < NS_TILES; s++) {
        const __half* Ks = hsm + ((s & 1) ? KS1_OFF_H : KS0_OFF_H);
        const __half* Vs = hsm + ((s & 1) ? VS1_OFF_H : VS0_OFF_H);

        // ---- QK^T ----
        float sc[16][4];
        #pragma unroll
        for (int nt = 0; nt < 16; nt++)
            #pragma unroll
            for (int f = 0; f < 4; f++) sc[nt][f] = 0.0f;

        #pragma unroll
        for (int nt = 0; nt < 16; nt++) {
            const __half* kp = Ks + (nt * 8 + g) * KS_STR + 2 * t;
            #pragma unroll
            for (int ks = 0; ks < 4; ks++) {
                const uint32_t b0 = ldh2(kp + 16 * ks);
                const uint32_t b1 = ldh2(kp + 16 * ks + 8);
                mma_f16(sc[nt], qa[ks][0], qa[ks][1], qa[ks][2], qa[ks][3], b0, b1);
            }
        }

        // ---- online softmax ----
        float tm0 = -1e30f, tm1 = -1e30f;
        #pragma unroll
        for (int nt = 0; nt < 16; nt++) {
            tm0 = fmaxf(tm0, fmaxf(sc[nt][0], sc[nt][1]));
            tm1 = fmaxf(tm1, fmaxf(sc[nt][2], sc[nt][3]));
        }
        tm0 = fmaxf(tm0, __shfl_xor_sync(0xffffffffu, tm0, 1));
        tm0 = fmaxf(tm0, __shfl_xor_sync(0xffffffffu, tm0, 2));
        tm1 = fmaxf(tm1, __shfl_xor_sync(0xffffffffu, tm1, 1));
        tm1 = fmaxf(tm1, __shfl_xor_sync(0xffffffffu, tm1, 2));
        const float nm0 = fmaxf(m0, tm0);
        const float nm1 = fmaxf(m1, tm1);
        const float corr0 = __expf(m0 - nm0);
        const float corr1 = __expf(m1 - nm1);
        m0 = nm0; m1 = nm1;

        float rs0 = 0.0f, rs1 = 0.0f;
        #pragma unroll
        for (int nt = 0; nt < 16; nt++) {
            sc[nt][0] = __expf(sc[nt][0] - m0); rs0 += sc[nt][0];
            sc[nt][1] = __expf(sc[nt][1] - m0); rs0 += sc[nt][1];
            sc[nt][2] = __expf(sc[nt][2] - m1); rs1 += sc[nt][2];
            sc[nt][3] = __expf(sc[nt][3] - m1); rs1 += sc[nt][3];
        }
        rs0 += __shfl_xor_sync(0xffffffffu, rs0, 1);
        rs0 += __shfl_xor_sync(0xffffffffu, rs0, 2);
        rs1 += __shfl_xor_sync(0xffffffffu, rs1, 1);
        rs1 += __shfl_xor_sync(0xffffffffu, rs1, 2);
        l0 = l0 * corr0 + rs0;
        l1 = l1 * corr1 + rs1;

        #pragma unroll
        for (int ct = 0; ct < 8; ct++) {
            av[ct][0] *= corr0; av[ct][1] *= corr0;
            av[ct][2] *= corr1; av[ct][3] *= corr1;
        }

        // ---- P -> half into Ps (warp-private rows) ----
        #pragma unroll
        for (int nt = 0; nt < 16; nt++) {
            *(__half2*)(Ps + (qrow + g) * PS_STR + nt * 8 + 2 * t) =
                __floats2half2_rn(sc[nt][0], sc[nt][1]);
            *(__half2*)(Ps + (qrow + g + 8) * PS_STR + nt * 8 + 2 * t) =
                __floats2half2_rn(sc[nt][2], sc[nt][3]);
        }
        __syncwarp();

        uint32_t pa[8][4];
        #pragma unroll
        for (int ks = 0; ks < 8; ks++) {
            const __half* pp = Ps + (qrow + g) * PS_STR + 16 * ks + 2 * t;
            pa[ks][0] = ldh2(pp);
            pa[ks][1] = ldh2(pp + 8 * PS_STR);
            pa[ks][2] = ldh2(pp + 8);
            pa[ks][3] = ldh2(pp + 8 * PS_STR + 8);
        }

        // ---- AV ----
        #pragma unroll
        for (int ct = 0; ct < 8; ct++) {
            const __half* vp = Vs + (ct * 8 + g) * VS_STR + 2 * t;
            #pragma unroll
            for (int ks = 0; ks < 8; ks++) {
                const uint32_t b0 = ldh2(vp + 16 * ks);
                const uint32_t b1 = ldh2(vp + 16 * ks + 8);
                mma_f16(av[ct], pa[ks][0], pa[ks][1], pa[ks][2], pa[ks][3], b0, b1);
            }
        }

        // ---- pipeline: free this buffer, issue s+2 into it, land s+1 ----
        if (s + 1 < NS_TILES) {
            __syncthreads();                 // all warps done reading buf s&1
            if (s + 2 < NS_TILES) {
                KV_ISSUE(s + 2, s & 1);      // overwrite buf s&1
                cpa_wait1();                 // KV(s+1) landed, KV(s+2) in flight
            } else {
                cpa_wait0();
            }
            __syncthreads();                 // KV(s+1) visible to all warps
        }
    }
    #undef KV_ISSUE

    const float inv0 = 1.0f / l0;
    const float inv1 = 1.0f / l1;
    #pragma unroll
    for (int ct = 0; ct < 8; ct++) {
        const int col = h * EDIM + ct * 8 + 2 * t;
        __half* o0 = go + (size_t)(b * LSEQ + q0 + qrow + g) * DMODEL + col;
        __half* o1 = go + (size_t)(b * LSEQ + q0 + qrow + g + 8) * DMODEL + col;
        *(__half2*)o0 = __floats2half2_rn(av[ct][0] * inv0, av[ct][1] * inv0);
        *(__half2*)o1 = __floats2half2_rn(av[ct][2] * inv1, av[ct][3] * inv1);
    }
}

extern "C" void kernel_launch(void* const* d_in, const int* in_sizes, int n_in,
                              void* d_out, int out_size)
{
    (void)in_sizes; (void)n_in; (void)out_size;
    const float* queries = (const float*)d_in[0];
    const float* keys    = (const float*)d_in[1];
    const float* values  = (const float*)d_in[2];
    const float* Wq = (const float*)d_in[3];
    const float* bq = (const float*)d_in[4];
    const float* Wk = (const float*)d_in[5];
    const float* bk = (const float*)d_in[6];
    const float* Wv = (const float*)d_in[7];
    const float* bv = (const float*)d_in[8];
    const float* Wo = (const float*)d_in[9];
    const float* bo = (const float*)d_in[10];
    float* out = (float*)d_out;

    __half *inq, *ink, *inv, *qh, *kh, *vT, *ah, *whq, *whk, *whv, *who;
    cudaGetSymbolAddress((void**)&inq, g_inq);
    cudaGetSymbolAddress((void**)&ink, g_ink);
    cudaGetSymbolAddress((void**)&inv, g_inv);
    cudaGetSymbolAddress((void**)&qh,  g_qh);
    cudaGetSymbolAddress((void**)&kh,  g_kh);
    cudaGetSymbolAddress((void**)&vT,  g_vT);
    cudaGetSymbolAddress((void**)&ah,  g_ah);
    cudaGetSymbolAddress((void**)&whq, g_whq);
    cudaGetSymbolAddress((void**)&whk, g_whk);
    cudaGetSymbolAddress((void**)&whv, g_whv);
    cudaGetSymbolAddress((void**)&who, g_who);

    cudaFuncSetAttribute(gemm_f16_kernel,
                         cudaFuncAttributeMaxDynamicSharedMemorySize, GSM_BYTES);
    cudaFuncSetAttribute(attn_f16_kernel,
                         cudaFuncAttributeMaxDynamicSharedMemorySize, ATTN_SMEM_BYTES);

    WC4 wc;
    wc.src[0] = Wq;  wc.src[1] = Wk;  wc.src[2] = Wv;  wc.src[3] = Wo;
    wc.dst[0] = whq; wc.dst[1] = whk; wc.dst[2] = whv; wc.dst[3] = who;
    wc.scale[0] = 0.125f; wc.scale[1] = 1.0f; wc.scale[2] = 1.0f; wc.scale[3] = 1.0f;
    wconv_kernel<<<dim3(32, 32, 4), dim3(32, 8)>>>(wc);

    AC3 ac;
    ac.src[0] = queries; ac.src[1] = keys; ac.src[2] = values;
    ac.dst[0] = inq;     ac.dst[1] = ink;  ac.dst[2] = inv;
    aconv_kernel<<<dim3(MTOT * DMODEL / (256 * 8), 3), 256>>>(ac);

    G4 pq;
    pq.A[0] = inq; pq.A[1] = ink; pq.A[2] = inv;
    pq.W[0] = whq; pq.W[1] = whk; pq.W[2] = whv;
    pq.bias[0] = bq; pq.bias[1] = bk; pq.bias[2] = bv;
    pq.bscale[0] = 0.125f; pq.bscale[1] = 1.0f; pq.bscale[2] = 1.0f;
    pq.Ch[0] = qh; pq.Ch[1] = kh; pq.Ch[2] = vT;
    pq.Cf[0] = pq.Cf[1] = pq.Cf[2] = nullptr;
    pq.mode[0] = 0; pq.mode[1] = 0; pq.mode[2] = 1;
    gemm_f16_kernel<<<dim3(8, 64, 3), 256, GSM_BYTES>>>(pq);

    attn_f16_kernel<<<dim3(LSEQ / 128, BATCH * NHEAD), 256, ATTN_SMEM_BYTES>>>(
        qh, kh, vT, ah);

    G4 po;
    po.A[0] = po.A[1] = po.A[2] = ah;
    po.W[0] = po.W[1] = po.W[2] = who;
    po.bias[0] = po.bias[1] = po.bias[2] = bo;
    po.bscale[0] = po.bscale[1] = po.bscale[2] = 1.0f;
    po.Ch[0] = po.Ch[1] = po.Ch[2] = nullptr;
    po.Cf[0] = po.Cf[1] = po.Cf[2] = out;
    po.mode[0] = po.mode[1] = po.mode[2] = 2;
    gemm_f16_kernel<<<dim3(8, 64, 1), 256, GSM_BYTES>>>(po);
}